// round 4
// baseline (speedup 1.0000x reference)
#include <cuda_runtime.h>
#include <cstdint>

// Problem constants (fixed by reference setup_inputs)
#define NTOK 16384
#define DM   1280
#define NH   16
#define HK   80
#define NSEGS 8
#define SEGL 2048

#define NEG_INF (__int_as_float(0xff800000))

// Scratch (allocation-free rule: __device__ globals)
__device__ float g_qkv[(size_t)NTOK * 3 * DM];   // [N][3*1280]
__device__ float g_ao [(size_t)NTOK * DM];       // attention output [N][1280]

// ---------------------------------------------------------------------------
// Packed f32x2 helpers (Blackwell FFMA2 path; PTX ISA 8.6, sm_100+ non-'a')
// ---------------------------------------------------------------------------
__device__ __forceinline__ uint64_t pack2(float lo, float hi) {
    uint64_t r;
    asm("mov.b64 %0, {%1, %2};" : "=l"(r) : "f"(lo), "f"(hi));
    return r;
}
__device__ __forceinline__ void unpack2(uint64_t v, float& lo, float& hi) {
    asm("mov.b64 {%0, %1}, %2;" : "=f"(lo), "=f"(hi) : "l"(v));
}
__device__ __forceinline__ void fma2(uint64_t& d, uint64_t a, uint64_t b) {
    asm("fma.rn.f32x2 %0, %1, %2, %0;" : "+l"(d) : "l"(a), "l"(b));
}
__device__ __forceinline__ void mul2(uint64_t& d, uint64_t a) {
    asm("mul.rn.f32x2 %0, %0, %1;" : "+l"(d) : "l"(a));
}

// ---------------------------------------------------------------------------
// GEMM with bias: C[M,N] = A[M,Kd] @ B[Kd,N] + bias[N]
// 128x128 tile, BK=8, 256 threads, 8x8 per thread (as 8x4 f32x2 pairs),
// double-buffered smem. FFMA2 inner loop.
// ---------------------------------------------------------------------------
__global__ __launch_bounds__(256) void gemm_bias_kernel(
    const float* __restrict__ A, const float* __restrict__ B,
    const float* __restrict__ bias, float* __restrict__ C,
    int M, int N, int Kd)
{
    __shared__ float As[2][8][128];
    __shared__ float Bs[2][8][128];
    const int tid = threadIdx.x;
    const int bx = blockIdx.x, by = blockIdx.y;

    const int arow = tid >> 1;
    const int acol = (tid & 1) << 2;
    const int brow = tid >> 5;
    const int bcol = (tid & 31) << 2;

    const float* Aptr = A + (size_t)(by * 128 + arow) * Kd + acol;
    const float* Bptr = B + (size_t)brow * N + bx * 128 + bcol;

    const int tx = tid & 15;
    const int ty = tid >> 4;

    uint64_t acc2[8][4];
#pragma unroll
    for (int i = 0; i < 8; i++)
#pragma unroll
        for (int j = 0; j < 4; j++) acc2[i][j] = 0ull;

    const int nt = Kd >> 3;

    float4 ra = *(const float4*)Aptr;
    float4 rb = *(const float4*)Bptr;
    As[0][acol + 0][arow] = ra.x;
    As[0][acol + 1][arow] = ra.y;
    As[0][acol + 2][arow] = ra.z;
    As[0][acol + 3][arow] = ra.w;
    *(float4*)&Bs[0][brow][bcol] = rb;
    __syncthreads();

    for (int t = 0; t < nt; ++t) {
        const int buf = t & 1;
        if (t + 1 < nt) {
            ra = *(const float4*)(Aptr + (t + 1) * 8);
            rb = *(const float4*)(Bptr + (size_t)(t + 1) * 8 * N);
        }
#pragma unroll
        for (int kk = 0; kk < 8; ++kk) {
            float4 a0 = *(const float4*)&As[buf][kk][ty * 4];
            float4 a1 = *(const float4*)&As[buf][kk][64 + ty * 4];
            float4 b0 = *(const float4*)&Bs[buf][kk][tx * 4];
            float4 b1 = *(const float4*)&Bs[buf][kk][64 + tx * 4];
            uint64_t bd[4];
            bd[0] = pack2(b0.x, b0.y);
            bd[1] = pack2(b0.z, b0.w);
            bd[2] = pack2(b1.x, b1.y);
            bd[3] = pack2(b1.z, b1.w);
            float av[8] = {a0.x, a0.y, a0.z, a0.w, a1.x, a1.y, a1.z, a1.w};
#pragma unroll
            for (int i = 0; i < 8; i++) {
                const uint64_t ad = pack2(av[i], av[i]);
#pragma unroll
                for (int j = 0; j < 4; j++)
                    fma2(acc2[i][j], ad, bd[j]);
            }
        }
        if (t + 1 < nt) {
            const int nb = buf ^ 1;
            As[nb][acol + 0][arow] = ra.x;
            As[nb][acol + 1][arow] = ra.y;
            As[nb][acol + 2][arow] = ra.z;
            As[nb][acol + 3][arow] = ra.w;
            *(float4*)&Bs[nb][brow][bcol] = rb;
            __syncthreads();
        }
    }

    // epilogue: unpack pairs; pair p of jj covers cols jj*64 + tx*4 + 2p..2p+1
#pragma unroll
    for (int ii = 0; ii < 2; ii++) {
#pragma unroll
        for (int i = 0; i < 4; i++) {
            const int row = by * 128 + ii * 64 + ty * 4 + i;
            float* cp = C + (size_t)row * N + bx * 128;
#pragma unroll
            for (int jj = 0; jj < 2; jj++) {
                const int c0 = jj * 64 + tx * 4;
                float4 v;
                unpack2(acc2[ii * 4 + i][jj * 2 + 0], v.x, v.y);
                unpack2(acc2[ii * 4 + i][jj * 2 + 1], v.z, v.w);
                v.x += bias[bx * 128 + c0 + 0];
                v.y += bias[bx * 128 + c0 + 1];
                v.z += bias[bx * 128 + c0 + 2];
                v.w += bias[bx * 128 + c0 + 3];
                *(float4*)(cp + c0) = v;
            }
        }
    }
}

// ---------------------------------------------------------------------------
// RoPE in-place on q and k parts of g_qkv.
// ---------------------------------------------------------------------------
__global__ __launch_bounds__(256) void rope_kernel(
    const float* __restrict__ cosNK, const float* __restrict__ sinNK)
{
    const int t = blockIdx.x * blockDim.x + threadIdx.x;
    if (t >= NTOK * NH * 40) return;
    const int j = t % 40;
    const int h = (t / 40) % NH;
    const int n = t / (40 * NH);

    const float c1 = cosNK[n * HK + j];
    const float s1 = sinNK[n * HK + j];
    const float c2 = cosNK[n * HK + j + 40];
    const float s2 = sinNK[n * HK + j + 40];

    size_t base = (size_t)n * (3 * DM) + h * HK;
    {
        float x1 = g_qkv[base + j], x2 = g_qkv[base + j + 40];
        g_qkv[base + j]      = x1 * c1 - x2 * s1;
        g_qkv[base + j + 40] = x2 * c2 + x1 * s2;
    }
    base += DM;
    {
        float x1 = g_qkv[base + j], x2 = g_qkv[base + j + 40];
        g_qkv[base + j]      = x1 * c1 - x2 * s1;
        g_qkv[base + j + 40] = x2 * c2 + x1 * s2;
    }
}

// ---------------------------------------------------------------------------
// Flash attention (fp32, online softmax) with FFMA2 inner loops.
// ---------------------------------------------------------------------------
#define BM 64
#define BN 64
#define QP 81
#define VP 80
#define PP 65

__global__ __launch_bounds__(256) void attn_kernel(
    const float* __restrict__ qkv, float* __restrict__ ao)
{
    extern __shared__ float smf[];
    float* Qs = smf;
    float* Ks = Qs + BM * QP;
    float* Vs = Ks + BN * QP;
    float* Ps = Vs + BN * VP;

    const int tid = threadIdx.x;
    const int qt = blockIdx.x, head = blockIdx.y, seg = blockIdx.z;
    const int n0 = seg * SEGL + qt * BM;

    const float scale = 0.1118033988749895f;

    for (int idx = tid; idx < BM * HK; idx += 256) {
        const int r = idx / HK, c = idx % HK;
        Qs[r * QP + c] = qkv[(size_t)(n0 + r) * (3 * DM) + head * HK + c] * scale;
    }

    const int lx = tid & 15;
    const int row0 = (tid >> 4) * 4;

    // O accumulator: cols lx+16*{0,1} / {2,3} packed, col lx+64 scalar
    uint64_t o2[4][2];
    float o4[4];
    float mrow[4], lrow[4];
#pragma unroll
    for (int i = 0; i < 4; i++) {
        mrow[i] = NEG_INF;
        lrow[i] = 0.f;
        o2[i][0] = 0ull;
        o2[i][1] = 0ull;
        o4[i] = 0.f;
    }
    __syncthreads();

    for (int kb = 0; kb < SEGL / BN; ++kb) {
        const int nk = seg * SEGL + kb * BN;
        for (int idx = tid; idx < BN * HK; idx += 256) {
            const int r = idx / HK, c = idx % HK;
            const size_t gb = (size_t)(nk + r) * (3 * DM) + head * HK + c;
            Ks[r * QP + c] = qkv[gb + DM];
            Vs[r * VP + c] = qkv[gb + 2 * DM];
        }
        __syncthreads();

        // S = (Q*scale) @ K^T ; packed over key pairs (lx+0,lx+16) and (lx+32,lx+48)
        uint64_t s2[4][2];
#pragma unroll
        for (int i = 0; i < 4; i++) { s2[i][0] = 0ull; s2[i][1] = 0ull; }

#pragma unroll 4
        for (int kk = 0; kk < HK; ++kk) {
            uint64_t kd[2];
            kd[0] = pack2(Ks[(lx +  0) * QP + kk], Ks[(lx + 16) * QP + kk]);
            kd[1] = pack2(Ks[(lx + 32) * QP + kk], Ks[(lx + 48) * QP + kk]);
#pragma unroll
            for (int i = 0; i < 4; i++) {
                const float qv = Qs[(row0 + i) * QP + kk];
                const uint64_t qd = pack2(qv, qv);
                fma2(s2[i][0], qd, kd[0]);
                fma2(s2[i][1], qd, kd[1]);
            }
        }

        // Online softmax update per row
#pragma unroll
        for (int i = 0; i < 4; i++) {
            float s[4];
            unpack2(s2[i][0], s[0], s[1]);
            unpack2(s2[i][1], s[2], s[3]);
            float mi = fmaxf(fmaxf(s[0], s[1]), fmaxf(s[2], s[3]));
            mi = fmaxf(mi, __shfl_xor_sync(0xffffffffu, mi, 1));
            mi = fmaxf(mi, __shfl_xor_sync(0xffffffffu, mi, 2));
            mi = fmaxf(mi, __shfl_xor_sync(0xffffffffu, mi, 4));
            mi = fmaxf(mi, __shfl_xor_sync(0xffffffffu, mi, 8));
            const float mnew = fmaxf(mrow[i], mi);
            const float corr = __expf(mrow[i] - mnew);
            float rs = 0.f;
#pragma unroll
            for (int j = 0; j < 4; j++) {
                s[j] = __expf(s[j] - mnew);
                rs += s[j];
            }
            rs += __shfl_xor_sync(0xffffffffu, rs, 1);
            rs += __shfl_xor_sync(0xffffffffu, rs, 2);
            rs += __shfl_xor_sync(0xffffffffu, rs, 4);
            rs += __shfl_xor_sync(0xffffffffu, rs, 8);
            lrow[i] = lrow[i] * corr + rs;
            mrow[i] = mnew;
            const uint64_t cd = pack2(corr, corr);
            mul2(o2[i][0], cd);
            mul2(o2[i][1], cd);
            o4[i] *= corr;
            // store s: cols lx+16j, s[j] maps to key (lx + 16*j)
            Ps[(row0 + i) * PP + lx +  0] = s[0];
            Ps[(row0 + i) * PP + lx + 16] = s[1];
            Ps[(row0 + i) * PP + lx + 32] = s[2];
            Ps[(row0 + i) * PP + lx + 48] = s[3];
        }
        __syncthreads();

        // O += P @ V ; out cols lx+16*{0..3} packed + lx+64 scalar
#pragma unroll 4
        for (int kk = 0; kk < BN; ++kk) {
            uint64_t vd[2];
            vd[0] = pack2(Vs[kk * VP + lx +  0], Vs[kk * VP + lx + 16]);
            vd[1] = pack2(Vs[kk * VP + lx + 32], Vs[kk * VP + lx + 48]);
            const float v4 = Vs[kk * VP + lx + 64];
#pragma unroll
            for (int i = 0; i < 4; i++) {
                const float p = Ps[(row0 + i) * PP + kk];
                const uint64_t pd = pack2(p, p);
                fma2(o2[i][0], pd, vd[0]);
                fma2(o2[i][1], pd, vd[1]);
                o4[i] = fmaf(p, v4, o4[i]);
            }
        }
        __syncthreads();
    }

    // Write normalized output
#pragma unroll
    for (int i = 0; i < 4; i++) {
        const float inv = 1.f / lrow[i];
        float a, b, c, d;
        unpack2(o2[i][0], a, b);
        unpack2(o2[i][1], c, d);
        float* op = ao + (size_t)(n0 + row0 + i) * DM + head * HK;
        op[lx +  0] = a * inv;
        op[lx + 16] = b * inv;
        op[lx + 32] = c * inv;
        op[lx + 48] = d * inv;
        op[lx + 64] = o4[i] * inv;
    }
}

// ---------------------------------------------------------------------------
// Launch
// ---------------------------------------------------------------------------
extern "C" void kernel_launch(void* const* d_in, const int* in_sizes, int n_in,
                              void* d_out, int out_size)
{
    const float* hidden = (const float*)d_in[0];
    const float* cosNK  = (const float*)d_in[1];
    const float* sinNK  = (const float*)d_in[2];
    const float* qkv_w  = (const float*)d_in[3];
    const float* qkv_b  = (const float*)d_in[4];
    const float* proj_w = (const float*)d_in[5];
    const float* proj_b = (const float*)d_in[6];
    float* out = (float*)d_out;

    float* qkv = nullptr;
    float* ao  = nullptr;
    cudaGetSymbolAddress((void**)&qkv, g_qkv);
    cudaGetSymbolAddress((void**)&ao,  g_ao);

    const int attn_smem = (BM * QP + BN * QP + BN * VP + BM * PP) * (int)sizeof(float);
    cudaFuncSetAttribute(attn_kernel, cudaFuncAttributeMaxDynamicSharedMemorySize, attn_smem);

    // 1) qkv = hidden @ qkv_w + qkv_b   (16384 x 3840)
    gemm_bias_kernel<<<dim3(3 * DM / 128, NTOK / 128), 256>>>(
        hidden, qkv_w, qkv_b, qkv, NTOK, 3 * DM, DM);

    // 2) RoPE on q,k
    {
        const int total = NTOK * NH * 40;
        rope_kernel<<<(total + 255) / 256, 256>>>(cosNK, sinNK);
    }

    // 3) attention per (segment, head, qtile)
    attn_kernel<<<dim3(SEGL / BM, NH, NSEGS), 256, attn_smem>>>(qkv, ao);

    // 4) out = ao @ proj_w + proj_b   (16384 x 1280)
    gemm_bias_kernel<<<dim3(DM / 128, NTOK / 128), 256>>>(
        ao, proj_w, proj_b, out, NTOK, DM, DM);
}

// round 5
// speedup vs baseline: 1.2373x; 1.2373x over previous
#include <cuda_runtime.h>
#include <cuda_bf16.h>
#include <cstdint>

// Problem constants (fixed by reference setup_inputs)
#define NTOK 16384
#define DM   1280
#define NH   16
#define HK   80
#define NSEGS 8
#define SEGL 2048

#define NEG_INF (__int_as_float(0xff800000))

// Scratch (allocation-free rule: __device__ globals)
__device__ float g_qkv[(size_t)NTOK * 3 * DM];            // [N][3*1280]
__device__ float g_ao [(size_t)NTOK * DM];                // attention output [N][1280]
__device__ __nv_bfloat16 g_ah[(size_t)NTOK * DM];         // A hi split
__device__ __nv_bfloat16 g_al[(size_t)NTOK * DM];         // A lo split
__device__ __nv_bfloat16 g_bh[(size_t)3 * DM * DM];       // W^T hi split [N][K]
__device__ __nv_bfloat16 g_bl[(size_t)3 * DM * DM];       // W^T lo split [N][K]

// ---------------------------------------------------------------------------
// helpers
// ---------------------------------------------------------------------------
__device__ __forceinline__ uint32_t smem_u32(const void* p) {
    uint32_t a;
    asm("{ .reg .u64 t; cvta.to.shared.u64 t, %1; cvt.u32.u64 %0, t; }" : "=r"(a) : "l"(p));
    return a;
}
__device__ __forceinline__ void ldsm4(uint32_t* r, uint32_t addr) {
    asm volatile("ldmatrix.sync.aligned.m8n8.x4.shared.b16 {%0,%1,%2,%3}, [%4];"
                 : "=r"(r[0]), "=r"(r[1]), "=r"(r[2]), "=r"(r[3]) : "r"(addr));
}
__device__ __forceinline__ void mma16816(float* d, const uint32_t* a, uint32_t b0, uint32_t b1) {
    asm volatile("mma.sync.aligned.m16n8k16.row.col.f32.bf16.bf16.f32 "
                 "{%0,%1,%2,%3}, {%4,%5,%6,%7}, {%8,%9}, {%0,%1,%2,%3};"
                 : "+f"(d[0]), "+f"(d[1]), "+f"(d[2]), "+f"(d[3])
                 : "r"(a[0]), "r"(a[1]), "r"(a[2]), "r"(a[3]), "r"(b0), "r"(b1));
}
// packed f32x2 (kept for attention)
__device__ __forceinline__ uint64_t pack2(float lo, float hi) {
    uint64_t r;
    asm("mov.b64 %0, {%1, %2};" : "=l"(r) : "f"(lo), "f"(hi));
    return r;
}
__device__ __forceinline__ void unpack2(uint64_t v, float& lo, float& hi) {
    asm("mov.b64 {%0, %1}, %2;" : "=f"(lo), "=f"(hi) : "l"(v));
}
__device__ __forceinline__ void fma2(uint64_t& d, uint64_t a, uint64_t b) {
    asm("fma.rn.f32x2 %0, %1, %2, %0;" : "+l"(d) : "l"(a), "l"(b));
}
__device__ __forceinline__ void mul2(uint64_t& d, uint64_t a) {
    asm("mul.rn.f32x2 %0, %0, %1;" : "+l"(d) : "l"(a));
}

// ---------------------------------------------------------------------------
// split: fp32 -> bf16 hi + bf16 lo (same layout), vectorized by 4
// ---------------------------------------------------------------------------
__global__ __launch_bounds__(256) void split_kernel(
    const float* __restrict__ in, __nv_bfloat16* __restrict__ hi,
    __nv_bfloat16* __restrict__ lo, int n4)
{
    const int i = blockIdx.x * blockDim.x + threadIdx.x;
    if (i >= n4) return;
    const float4 v = ((const float4*)in)[i];
    __nv_bfloat16 h0 = __float2bfloat16(v.x);
    __nv_bfloat16 h1 = __float2bfloat16(v.y);
    __nv_bfloat16 h2 = __float2bfloat16(v.z);
    __nv_bfloat16 h3 = __float2bfloat16(v.w);
    __nv_bfloat16 l0 = __float2bfloat16(v.x - __bfloat162float(h0));
    __nv_bfloat16 l1 = __float2bfloat16(v.y - __bfloat162float(h1));
    __nv_bfloat16 l2 = __float2bfloat16(v.z - __bfloat162float(h2));
    __nv_bfloat16 l3 = __float2bfloat16(v.w - __bfloat162float(h3));
    __nv_bfloat162 hp0 = {h0, h1}, hp1 = {h2, h3};
    __nv_bfloat162 lp0 = {l0, l1}, lp1 = {l2, l3};
    ((__nv_bfloat162*)hi)[i * 2 + 0] = hp0;
    ((__nv_bfloat162*)hi)[i * 2 + 1] = hp1;
    ((__nv_bfloat162*)lo)[i * 2 + 0] = lp0;
    ((__nv_bfloat162*)lo)[i * 2 + 1] = lp1;
}

// ---------------------------------------------------------------------------
// transpose + split: W[K][N] row-major -> WT hi/lo [N][K] bf16
// ---------------------------------------------------------------------------
__global__ void transpose_split_kernel(
    const float* __restrict__ W, __nv_bfloat16* __restrict__ bh,
    __nv_bfloat16* __restrict__ bl, int Krows, int Ncols)
{
    __shared__ float t[32][33];
    const int bx = blockIdx.x * 32;   // N offset
    const int by = blockIdx.y * 32;   // K offset
    const int x = threadIdx.x, y = threadIdx.y;
#pragma unroll
    for (int i = 0; i < 32; i += 8)
        t[y + i][x] = W[(size_t)(by + y + i) * Ncols + bx + x];
    __syncthreads();
#pragma unroll
    for (int i = 0; i < 32; i += 8) {
        const float v = t[x][y + i];
        const __nv_bfloat16 h = __float2bfloat16(v);
        const size_t o = (size_t)(bx + y + i) * Krows + by + x;
        bh[o] = h;
        bl[o] = __float2bfloat16(v - __bfloat162float(h));
    }
}

// ---------------------------------------------------------------------------
// bf16 3-split tensor-core GEMM + bias:
//   C[M,N] = A[M,K] @ WT[N,K]^T + bias[N],  A/WT given as hi/lo bf16 pairs.
// CTA 128x128, 8 warps (4x2), warp tile 32x64, K-chunk 32, double-buffered.
// smem pitch 40 bf16 (80B) -> conflict-free ldmatrix.
// ---------------------------------------------------------------------------
#define GP 40
#define BUFE (128 * GP)
#define GSMEM (8 * BUFE * 2)   // 8 tiles (A/B x hi/lo x 2 bufs) * bf16

__global__ __launch_bounds__(256) void gemm_mma(
    const __nv_bfloat16* __restrict__ Ah, const __nv_bfloat16* __restrict__ Al,
    const __nv_bfloat16* __restrict__ Bh, const __nv_bfloat16* __restrict__ Bl,
    const float* __restrict__ bias, float* __restrict__ C, int N, int Kd)
{
    extern __shared__ __nv_bfloat16 smb[];
    __nv_bfloat16* Ash = smb;
    __nv_bfloat16* Asl = Ash + 2 * BUFE;
    __nv_bfloat16* Bsh = Asl + 2 * BUFE;
    __nv_bfloat16* Bsl = Bsh + 2 * BUFE;

    const int tid = threadIdx.x;
    const int lane = tid & 31;
    const int warp = tid >> 5;
    const int wm = warp >> 1;          // 0..3
    const int wn = warp & 1;           // 0..1
    const int m0 = blockIdx.y * 128;
    const int n0 = blockIdx.x * 128;

    // global load mapping: 2 x 16B per array per thread
    const int r0 = tid >> 2;           // rows 0..63
    const int sg = (tid & 3) * 8;      // bf16 col offset (8 per 16B)

    const __nv_bfloat16* pAh = Ah + (size_t)(m0 + r0) * Kd + sg;
    const __nv_bfloat16* pAl = Al + (size_t)(m0 + r0) * Kd + sg;
    const __nv_bfloat16* pBh = Bh + (size_t)(n0 + r0) * Kd + sg;
    const __nv_bfloat16* pBl = Bl + (size_t)(n0 + r0) * Kd + sg;
    const size_t rstep = (size_t)64 * Kd;

    float acc[2][8][4];
#pragma unroll
    for (int a = 0; a < 2; a++)
#pragma unroll
        for (int b = 0; b < 8; b++)
#pragma unroll
            for (int c = 0; c < 4; c++) acc[a][b][c] = 0.f;

    uint4 vah0, vah1, val0, val1, vbh0, vbh1, vbl0, vbl1;
    auto load_chunk = [&](int k0) {
        vah0 = *(const uint4*)(pAh + k0);
        vah1 = *(const uint4*)(pAh + k0 + rstep);
        val0 = *(const uint4*)(pAl + k0);
        val1 = *(const uint4*)(pAl + k0 + rstep);
        vbh0 = *(const uint4*)(pBh + k0);
        vbh1 = *(const uint4*)(pBh + k0 + rstep);
        vbl0 = *(const uint4*)(pBl + k0);
        vbl1 = *(const uint4*)(pBl + k0 + rstep);
    };
    auto store_chunk = [&](int buf) {
        const int o0 = buf * BUFE + r0 * GP + sg;
        const int o1 = buf * BUFE + (r0 + 64) * GP + sg;
        *(uint4*)&Ash[o0] = vah0;  *(uint4*)&Ash[o1] = vah1;
        *(uint4*)&Asl[o0] = val0;  *(uint4*)&Asl[o1] = val1;
        *(uint4*)&Bsh[o0] = vbh0;  *(uint4*)&Bsh[o1] = vbh1;
        *(uint4*)&Bsl[o0] = vbl0;  *(uint4*)&Bsl[o1] = vbl1;
    };

    const uint32_t uAsh = smem_u32(Ash);
    const uint32_t uAsl = smem_u32(Asl);
    const uint32_t uBsh = smem_u32(Bsh);
    const uint32_t uBsl = smem_u32(Bsl);
    // ldmatrix per-lane offsets (bytes): row = (lane&15), khalf = (lane>>4)*8 elems
    const uint32_t aoff = (uint32_t)((wm * 32 + (lane & 15)) * GP + ((lane >> 4) << 3)) * 2;
    const uint32_t boff = (uint32_t)((wn * 64 + (lane & 15)) * GP + ((lane >> 4) << 3)) * 2;

    const int NT = Kd >> 5;

    load_chunk(0);
    store_chunk(0);
    __syncthreads();

    for (int t = 0; t < NT; ++t) {
        const int buf = t & 1;
        if (t + 1 < NT) load_chunk((t + 1) << 5);

        const uint32_t bb = (uint32_t)(buf * BUFE * 2);
#pragma unroll
        for (int ks = 0; ks < 2; ++ks) {
            const uint32_t kso = (uint32_t)(ks * 16 * 2);
            uint32_t ah[2][4], al[2][4];
#pragma unroll
            for (int t2 = 0; t2 < 2; ++t2) {
                const uint32_t ad = bb + aoff + kso + (uint32_t)(t2 * 16 * GP * 2);
                ldsm4(ah[t2], uAsh + ad);
                ldsm4(al[t2], uAsl + ad);
            }
            uint32_t bh4[4][4], bl4[4][4];
#pragma unroll
            for (int g = 0; g < 4; ++g) {
                const uint32_t bd = bb + boff + kso + (uint32_t)(g * 16 * GP * 2);
                ldsm4(bh4[g], uBsh + bd);
                ldsm4(bl4[g], uBsl + bd);
            }
#pragma unroll
            for (int t2 = 0; t2 < 2; ++t2)
#pragma unroll
                for (int g = 0; g < 4; ++g)
#pragma unroll
                    for (int h = 0; h < 2; ++h) {
                        float* d = acc[t2][g * 2 + h];
                        mma16816(d, ah[t2], bh4[g][h], bh4[g][h + 2]);
                        mma16816(d, ah[t2], bl4[g][h], bl4[g][h + 2]);
                        mma16816(d, al[t2], bh4[g][h], bh4[g][h + 2]);
                    }
        }

        if (t + 1 < NT) {
            store_chunk((t + 1) & 1);
            __syncthreads();
        }
    }

    // epilogue
#pragma unroll
    for (int t2 = 0; t2 < 2; ++t2) {
        const int row = m0 + wm * 32 + t2 * 16 + (lane >> 2);
#pragma unroll
        for (int n8 = 0; n8 < 8; ++n8) {
            const int col = n0 + wn * 64 + n8 * 8 + (lane & 3) * 2;
            const float b0 = __ldg(bias + col);
            const float b1 = __ldg(bias + col + 1);
            float2 v0 = {acc[t2][n8][0] + b0, acc[t2][n8][1] + b1};
            float2 v1 = {acc[t2][n8][2] + b0, acc[t2][n8][3] + b1};
            *(float2*)(C + (size_t)row * N + col) = v0;
            *(float2*)(C + (size_t)(row + 8) * N + col) = v1;
        }
    }
}

// ---------------------------------------------------------------------------
// RoPE in-place on q and k parts of g_qkv.
// ---------------------------------------------------------------------------
__global__ __launch_bounds__(256) void rope_kernel(
    const float* __restrict__ cosNK, const float* __restrict__ sinNK)
{
    const int t = blockIdx.x * blockDim.x + threadIdx.x;
    if (t >= NTOK * NH * 40) return;
    const int j = t % 40;
    const int h = (t / 40) % NH;
    const int n = t / (40 * NH);

    const float c1 = cosNK[n * HK + j];
    const float s1 = sinNK[n * HK + j];
    const float c2 = cosNK[n * HK + j + 40];
    const float s2 = sinNK[n * HK + j + 40];

    size_t base = (size_t)n * (3 * DM) + h * HK;
    {
        float x1 = g_qkv[base + j], x2 = g_qkv[base + j + 40];
        g_qkv[base + j]      = x1 * c1 - x2 * s1;
        g_qkv[base + j + 40] = x2 * c2 + x1 * s2;
    }
    base += DM;
    {
        float x1 = g_qkv[base + j], x2 = g_qkv[base + j + 40];
        g_qkv[base + j]      = x1 * c1 - x2 * s1;
        g_qkv[base + j + 40] = x2 * c2 + x1 * s2;
    }
}

// ---------------------------------------------------------------------------
// Flash attention (fp32, online softmax) with FFMA2 inner loops (unchanged).
// ---------------------------------------------------------------------------
#define BM 64
#define BN 64
#define QP 81
#define VP 80
#define PP 65

__global__ __launch_bounds__(256) void attn_kernel(
    const float* __restrict__ qkv, float* __restrict__ ao)
{
    extern __shared__ float smf[];
    float* Qs = smf;
    float* Ks = Qs + BM * QP;
    float* Vs = Ks + BN * QP;
    float* Ps = Vs + BN * VP;

    const int tid = threadIdx.x;
    const int qt = blockIdx.x, head = blockIdx.y, seg = blockIdx.z;
    const int n0 = seg * SEGL + qt * BM;

    const float scale = 0.1118033988749895f;

    for (int idx = tid; idx < BM * HK; idx += 256) {
        const int r = idx / HK, c = idx % HK;
        Qs[r * QP + c] = qkv[(size_t)(n0 + r) * (3 * DM) + head * HK + c] * scale;
    }

    const int lx = tid & 15;
    const int row0 = (tid >> 4) * 4;

    uint64_t o2[4][2];
    float o4[4];
    float mrow[4], lrow[4];
#pragma unroll
    for (int i = 0; i < 4; i++) {
        mrow[i] = NEG_INF;
        lrow[i] = 0.f;
        o2[i][0] = 0ull;
        o2[i][1] = 0ull;
        o4[i] = 0.f;
    }
    __syncthreads();

    for (int kb = 0; kb < SEGL / BN; ++kb) {
        const int nk = seg * SEGL + kb * BN;
        for (int idx = tid; idx < BN * HK; idx += 256) {
            const int r = idx / HK, c = idx % HK;
            const size_t gb = (size_t)(nk + r) * (3 * DM) + head * HK + c;
            Ks[r * QP + c] = qkv[gb + DM];
            Vs[r * VP + c] = qkv[gb + 2 * DM];
        }
        __syncthreads();

        uint64_t s2[4][2];
#pragma unroll
        for (int i = 0; i < 4; i++) { s2[i][0] = 0ull; s2[i][1] = 0ull; }

#pragma unroll 4
        for (int kk = 0; kk < HK; ++kk) {
            uint64_t kd[2];
            kd[0] = pack2(Ks[(lx +  0) * QP + kk], Ks[(lx + 16) * QP + kk]);
            kd[1] = pack2(Ks[(lx + 32) * QP + kk], Ks[(lx + 48) * QP + kk]);
#pragma unroll
            for (int i = 0; i < 4; i++) {
                const float qv = Qs[(row0 + i) * QP + kk];
                const uint64_t qd = pack2(qv, qv);
                fma2(s2[i][0], qd, kd[0]);
                fma2(s2[i][1], qd, kd[1]);
            }
        }

#pragma unroll
        for (int i = 0; i < 4; i++) {
            float s[4];
            unpack2(s2[i][0], s[0], s[1]);
            unpack2(s2[i][1], s[2], s[3]);
            float mi = fmaxf(fmaxf(s[0], s[1]), fmaxf(s[2], s[3]));
            mi = fmaxf(mi, __shfl_xor_sync(0xffffffffu, mi, 1));
            mi = fmaxf(mi, __shfl_xor_sync(0xffffffffu, mi, 2));
            mi = fmaxf(mi, __shfl_xor_sync(0xffffffffu, mi, 4));
            mi = fmaxf(mi, __shfl_xor_sync(0xffffffffu, mi, 8));
            const float mnew = fmaxf(mrow[i], mi);
            const float corr = __expf(mrow[i] - mnew);
            float rs = 0.f;
#pragma unroll
            for (int j = 0; j < 4; j++) {
                s[j] = __expf(s[j] - mnew);
                rs += s[j];
            }
            rs += __shfl_xor_sync(0xffffffffu, rs, 1);
            rs += __shfl_xor_sync(0xffffffffu, rs, 2);
            rs += __shfl_xor_sync(0xffffffffu, rs, 4);
            rs += __shfl_xor_sync(0xffffffffu, rs, 8);
            lrow[i] = lrow[i] * corr + rs;
            mrow[i] = mnew;
            const uint64_t cd = pack2(corr, corr);
            mul2(o2[i][0], cd);
            mul2(o2[i][1], cd);
            o4[i] *= corr;
            Ps[(row0 + i) * PP + lx +  0] = s[0];
            Ps[(row0 + i) * PP + lx + 16] = s[1];
            Ps[(row0 + i) * PP + lx + 32] = s[2];
            Ps[(row0 + i) * PP + lx + 48] = s[3];
        }
        __syncthreads();

#pragma unroll 4
        for (int kk = 0; kk < BN; ++kk) {
            uint64_t vd[2];
            vd[0] = pack2(Vs[kk * VP + lx +  0], Vs[kk * VP + lx + 16]);
            vd[1] = pack2(Vs[kk * VP + lx + 32], Vs[kk * VP + lx + 48]);
            const float v4 = Vs[kk * VP + lx + 64];
#pragma unroll
            for (int i = 0; i < 4; i++) {
                const float p = Ps[(row0 + i) * PP + kk];
                const uint64_t pd = pack2(p, p);
                fma2(o2[i][0], pd, vd[0]);
                fma2(o2[i][1], pd, vd[1]);
                o4[i] = fmaf(p, v4, o4[i]);
            }
        }
        __syncthreads();
    }

#pragma unroll
    for (int i = 0; i < 4; i++) {
        const float inv = 1.f / lrow[i];
        float a, b, c, d;
        unpack2(o2[i][0], a, b);
        unpack2(o2[i][1], c, d);
        float* op = ao + (size_t)(n0 + row0 + i) * DM + head * HK;
        op[lx +  0] = a * inv;
        op[lx + 16] = b * inv;
        op[lx + 32] = c * inv;
        op[lx + 48] = d * inv;
        op[lx + 64] = o4[i] * inv;
    }
}

// ---------------------------------------------------------------------------
// Launch
// ---------------------------------------------------------------------------
extern "C" void kernel_launch(void* const* d_in, const int* in_sizes, int n_in,
                              void* d_out, int out_size)
{
    const float* hidden = (const float*)d_in[0];
    const float* cosNK  = (const float*)d_in[1];
    const float* sinNK  = (const float*)d_in[2];
    const float* qkv_w  = (const float*)d_in[3];
    const float* qkv_b  = (const float*)d_in[4];
    const float* proj_w = (const float*)d_in[5];
    const float* proj_b = (const float*)d_in[6];
    float* out = (float*)d_out;

    float *qkv = nullptr, *ao = nullptr;
    __nv_bfloat16 *ah = nullptr, *al = nullptr, *bh = nullptr, *bl = nullptr;
    cudaGetSymbolAddress((void**)&qkv, g_qkv);
    cudaGetSymbolAddress((void**)&ao,  g_ao);
    cudaGetSymbolAddress((void**)&ah,  g_ah);
    cudaGetSymbolAddress((void**)&al,  g_al);
    cudaGetSymbolAddress((void**)&bh,  g_bh);
    cudaGetSymbolAddress((void**)&bl,  g_bl);

    const int attn_smem = (BM * QP + BN * QP + BN * VP + BM * PP) * (int)sizeof(float);
    cudaFuncSetAttribute(attn_kernel, cudaFuncAttributeMaxDynamicSharedMemorySize, attn_smem);
    cudaFuncSetAttribute(gemm_mma, cudaFuncAttributeMaxDynamicSharedMemorySize, GSMEM);

    const int n4 = NTOK * DM / 4;

    // 1) prep for GEMM1: split hidden, transpose+split qkv_w
    split_kernel<<<(n4 + 255) / 256, 256>>>(hidden, ah, al, n4);
    transpose_split_kernel<<<dim3(3 * DM / 32, DM / 32), dim3(32, 8)>>>(qkv_w, bh, bl, DM, 3 * DM);

    // 2) qkv = hidden @ qkv_w + qkv_b  (tensor cores, 3x bf16 split)
    gemm_mma<<<dim3(3 * DM / 128, NTOK / 128), 256, GSMEM>>>(
        ah, al, bh, bl, qkv_b, qkv, 3 * DM, DM);

    // 3) RoPE on q,k
    {
        const int total = NTOK * NH * 40;
        rope_kernel<<<(total + 255) / 256, 256>>>(cosNK, sinNK);
    }

    // 4) attention
    attn_kernel<<<dim3(SEGL / BM, NH, NSEGS), 256, attn_smem>>>(qkv, ao);

    // 5) prep for GEMM2: split ao, transpose+split proj_w (reuse buffers)
    split_kernel<<<(n4 + 255) / 256, 256>>>(ao, ah, al, n4);
    transpose_split_kernel<<<dim3(DM / 32, DM / 32), dim3(32, 8)>>>(proj_w, bh, bl, DM, DM);

    // 6) out = ao @ proj_w + proj_b  (tensor cores, 3x bf16 split)
    gemm_mma<<<dim3(DM / 128, NTOK / 128), 256, GSMEM>>>(
        ah, al, bh, bl, proj_b, out, DM, DM);
}

// round 6
// speedup vs baseline: 2.4025x; 1.9418x over previous
#include <cuda_runtime.h>
#include <cuda_bf16.h>
#include <cstdint>

// Problem constants (fixed by reference setup_inputs)
#define NTOK 16384
#define DM   1280
#define NH   16
#define HK   80
#define NSEGS 8
#define SEGL 2048

#define NEG_INF (__int_as_float(0xff800000))

// Scratch (allocation-free rule: __device__ globals)
__device__ float g_qkv[(size_t)NTOK * 3 * DM];            // [N][3*1280]
__device__ float g_ao [(size_t)NTOK * DM];                // attention output [N][1280]
__device__ __nv_bfloat16 g_ah[(size_t)NTOK * DM];         // A hi split
__device__ __nv_bfloat16 g_al[(size_t)NTOK * DM];         // A lo split
__device__ __nv_bfloat16 g_bh[(size_t)3 * DM * DM];       // W^T hi split [N][K]
__device__ __nv_bfloat16 g_bl[(size_t)3 * DM * DM];       // W^T lo split [N][K]

// ---------------------------------------------------------------------------
// helpers
// ---------------------------------------------------------------------------
__device__ __forceinline__ uint32_t smem_u32(const void* p) {
    uint32_t a;
    asm("{ .reg .u64 t; cvta.to.shared.u64 t, %1; cvt.u32.u64 %0, t; }" : "=r"(a) : "l"(p));
    return a;
}
__device__ __forceinline__ void ldsm4(uint32_t* r, uint32_t addr) {
    asm volatile("ldmatrix.sync.aligned.m8n8.x4.shared.b16 {%0,%1,%2,%3}, [%4];"
                 : "=r"(r[0]), "=r"(r[1]), "=r"(r[2]), "=r"(r[3]) : "r"(addr));
}
__device__ __forceinline__ void ldsm4t(uint32_t* r, uint32_t addr) {
    asm volatile("ldmatrix.sync.aligned.m8n8.x4.trans.shared.b16 {%0,%1,%2,%3}, [%4];"
                 : "=r"(r[0]), "=r"(r[1]), "=r"(r[2]), "=r"(r[3]) : "r"(addr));
}
__device__ __forceinline__ void mma16816(float* d, const uint32_t* a, uint32_t b0, uint32_t b1) {
    asm volatile("mma.sync.aligned.m16n8k16.row.col.f32.bf16.bf16.f32 "
                 "{%0,%1,%2,%3}, {%4,%5,%6,%7}, {%8,%9}, {%0,%1,%2,%3};"
                 : "+f"(d[0]), "+f"(d[1]), "+f"(d[2]), "+f"(d[3])
                 : "r"(a[0]), "r"(a[1]), "r"(a[2]), "r"(a[3]), "r"(b0), "r"(b1));
}
// pack two fp32 -> bf16x2 reg {hi, lo}
__device__ __forceinline__ uint32_t cvt_bf2(float hi, float lo) {
    uint32_t d;
    asm("cvt.rn.bf16x2.f32 %0, %1, %2;" : "=r"(d) : "f"(hi), "f"(lo));
    return d;
}
// FMA-pipe exp2 for t <= 0 (clamped), ~3e-6 rel error
__device__ __forceinline__ float exp2p(float t) {
    t = fmaxf(t, -126.f);
    const float z = t + 12582912.f;                       // round-to-nearest int
    const int n = __float_as_int(z) - 0x4B400000;
    const float f = t - (z - 12582912.f);                 // [-0.5, 0.5]
    float r = 1.3333558146e-3f;
    r = fmaf(r, f, 9.6181291076e-3f);
    r = fmaf(r, f, 5.5504108664e-2f);
    r = fmaf(r, f, 2.4022650695e-1f);
    r = fmaf(r, f, 6.9314718055e-1f);
    r = fmaf(r, f, 1.0f);
    return __int_as_float(__float_as_int(r) + (n << 23));
}

// ---------------------------------------------------------------------------
// split: fp32 -> bf16 hi + bf16 lo (same layout), vectorized by 4
// ---------------------------------------------------------------------------
__global__ __launch_bounds__(256) void split_kernel(
    const float* __restrict__ in, __nv_bfloat16* __restrict__ hi,
    __nv_bfloat16* __restrict__ lo, int n4)
{
    const int i = blockIdx.x * blockDim.x + threadIdx.x;
    if (i >= n4) return;
    const float4 v = ((const float4*)in)[i];
    __nv_bfloat16 h0 = __float2bfloat16(v.x);
    __nv_bfloat16 h1 = __float2bfloat16(v.y);
    __nv_bfloat16 h2 = __float2bfloat16(v.z);
    __nv_bfloat16 h3 = __float2bfloat16(v.w);
    __nv_bfloat16 l0 = __float2bfloat16(v.x - __bfloat162float(h0));
    __nv_bfloat16 l1 = __float2bfloat16(v.y - __bfloat162float(h1));
    __nv_bfloat16 l2 = __float2bfloat16(v.z - __bfloat162float(h2));
    __nv_bfloat16 l3 = __float2bfloat16(v.w - __bfloat162float(h3));
    __nv_bfloat162 hp0 = {h0, h1}, hp1 = {h2, h3};
    __nv_bfloat162 lp0 = {l0, l1}, lp1 = {l2, l3};
    ((__nv_bfloat162*)hi)[i * 2 + 0] = hp0;
    ((__nv_bfloat162*)hi)[i * 2 + 1] = hp1;
    ((__nv_bfloat162*)lo)[i * 2 + 0] = lp0;
    ((__nv_bfloat162*)lo)[i * 2 + 1] = lp1;
}

// ---------------------------------------------------------------------------
// transpose + split: W[K][N] row-major -> WT hi/lo [N][K] bf16
// ---------------------------------------------------------------------------
__global__ void transpose_split_kernel(
    const float* __restrict__ W, __nv_bfloat16* __restrict__ bh,
    __nv_bfloat16* __restrict__ bl, int Krows, int Ncols)
{
    __shared__ float t[32][33];
    const int bx = blockIdx.x * 32;
    const int by = blockIdx.y * 32;
    const int x = threadIdx.x, y = threadIdx.y;
#pragma unroll
    for (int i = 0; i < 32; i += 8)
        t[y + i][x] = W[(size_t)(by + y + i) * Ncols + bx + x];
    __syncthreads();
#pragma unroll
    for (int i = 0; i < 32; i += 8) {
        const float v = t[x][y + i];
        const __nv_bfloat16 h = __float2bfloat16(v);
        const size_t o = (size_t)(bx + y + i) * Krows + by + x;
        bh[o] = h;
        bl[o] = __float2bfloat16(v - __bfloat162float(h));
    }
}

// ---------------------------------------------------------------------------
// bf16 3-split tensor-core GEMM + bias (unchanged from R5)
// ---------------------------------------------------------------------------
#define GP 40
#define BUFE (128 * GP)
#define GSMEM (8 * BUFE * 2)

__global__ __launch_bounds__(256) void gemm_mma(
    const __nv_bfloat16* __restrict__ Ah, const __nv_bfloat16* __restrict__ Al,
    const __nv_bfloat16* __restrict__ Bh, const __nv_bfloat16* __restrict__ Bl,
    const float* __restrict__ bias, float* __restrict__ C, int N, int Kd)
{
    extern __shared__ __nv_bfloat16 smb[];
    __nv_bfloat16* Ash = smb;
    __nv_bfloat16* Asl = Ash + 2 * BUFE;
    __nv_bfloat16* Bsh = Asl + 2 * BUFE;
    __nv_bfloat16* Bsl = Bsh + 2 * BUFE;

    const int tid = threadIdx.x;
    const int lane = tid & 31;
    const int warp = tid >> 5;
    const int wm = warp >> 1;
    const int wn = warp & 1;
    const int m0 = blockIdx.y * 128;
    const int n0 = blockIdx.x * 128;

    const int r0 = tid >> 2;
    const int sg = (tid & 3) * 8;

    const __nv_bfloat16* pAh = Ah + (size_t)(m0 + r0) * Kd + sg;
    const __nv_bfloat16* pAl = Al + (size_t)(m0 + r0) * Kd + sg;
    const __nv_bfloat16* pBh = Bh + (size_t)(n0 + r0) * Kd + sg;
    const __nv_bfloat16* pBl = Bl + (size_t)(n0 + r0) * Kd + sg;
    const size_t rstep = (size_t)64 * Kd;

    float acc[2][8][4];
#pragma unroll
    for (int a = 0; a < 2; a++)
#pragma unroll
        for (int b = 0; b < 8; b++)
#pragma unroll
            for (int c = 0; c < 4; c++) acc[a][b][c] = 0.f;

    uint4 vah0, vah1, val0, val1, vbh0, vbh1, vbl0, vbl1;
    auto load_chunk = [&](int k0) {
        vah0 = *(const uint4*)(pAh + k0);
        vah1 = *(const uint4*)(pAh + k0 + rstep);
        val0 = *(const uint4*)(pAl + k0);
        val1 = *(const uint4*)(pAl + k0 + rstep);
        vbh0 = *(const uint4*)(pBh + k0);
        vbh1 = *(const uint4*)(pBh + k0 + rstep);
        vbl0 = *(const uint4*)(pBl + k0);
        vbl1 = *(const uint4*)(pBl + k0 + rstep);
    };
    auto store_chunk = [&](int buf) {
        const int o0 = buf * BUFE + r0 * GP + sg;
        const int o1 = buf * BUFE + (r0 + 64) * GP + sg;
        *(uint4*)&Ash[o0] = vah0;  *(uint4*)&Ash[o1] = vah1;
        *(uint4*)&Asl[o0] = val0;  *(uint4*)&Asl[o1] = val1;
        *(uint4*)&Bsh[o0] = vbh0;  *(uint4*)&Bsh[o1] = vbh1;
        *(uint4*)&Bsl[o0] = vbl0;  *(uint4*)&Bsl[o1] = vbl1;
    };

    const uint32_t uAsh = smem_u32(Ash);
    const uint32_t uAsl = smem_u32(Asl);
    const uint32_t uBsh = smem_u32(Bsh);
    const uint32_t uBsl = smem_u32(Bsl);
    const uint32_t aoff = (uint32_t)((wm * 32 + (lane & 15)) * GP + ((lane >> 4) << 3)) * 2;
    const uint32_t boff = (uint32_t)((wn * 64 + (lane & 15)) * GP + ((lane >> 4) << 3)) * 2;

    const int NT = Kd >> 5;

    load_chunk(0);
    store_chunk(0);
    __syncthreads();

    for (int t = 0; t < NT; ++t) {
        const int buf = t & 1;
        if (t + 1 < NT) load_chunk((t + 1) << 5);

        const uint32_t bb = (uint32_t)(buf * BUFE * 2);
#pragma unroll
        for (int ks = 0; ks < 2; ++ks) {
            const uint32_t kso = (uint32_t)(ks * 16 * 2);
            uint32_t ah[2][4], al[2][4];
#pragma unroll
            for (int t2 = 0; t2 < 2; ++t2) {
                const uint32_t ad = bb + aoff + kso + (uint32_t)(t2 * 16 * GP * 2);
                ldsm4(ah[t2], uAsh + ad);
                ldsm4(al[t2], uAsl + ad);
            }
            uint32_t bh4[4][4], bl4[4][4];
#pragma unroll
            for (int g = 0; g < 4; ++g) {
                const uint32_t bd = bb + boff + kso + (uint32_t)(g * 16 * GP * 2);
                ldsm4(bh4[g], uBsh + bd);
                ldsm4(bl4[g], uBsl + bd);
            }
#pragma unroll
            for (int t2 = 0; t2 < 2; ++t2)
#pragma unroll
                for (int g = 0; g < 4; ++g)
#pragma unroll
                    for (int h = 0; h < 2; ++h) {
                        float* d = acc[t2][g * 2 + h];
                        mma16816(d, ah[t2], bh4[g][h], bh4[g][h + 2]);
                        mma16816(d, ah[t2], bl4[g][h], bl4[g][h + 2]);
                        mma16816(d, al[t2], bh4[g][h], bh4[g][h + 2]);
                    }
        }

        if (t + 1 < NT) {
            store_chunk((t + 1) & 1);
            __syncthreads();
        }
    }

#pragma unroll
    for (int t2 = 0; t2 < 2; ++t2) {
        const int row = m0 + wm * 32 + t2 * 16 + (lane >> 2);
#pragma unroll
        for (int n8 = 0; n8 < 8; ++n8) {
            const int col = n0 + wn * 64 + n8 * 8 + (lane & 3) * 2;
            const float b0 = __ldg(bias + col);
            const float b1 = __ldg(bias + col + 1);
            float2 v0 = {acc[t2][n8][0] + b0, acc[t2][n8][1] + b1};
            float2 v1 = {acc[t2][n8][2] + b0, acc[t2][n8][3] + b1};
            *(float2*)(C + (size_t)row * N + col) = v0;
            *(float2*)(C + (size_t)(row + 8) * N + col) = v1;
        }
    }
}

// ---------------------------------------------------------------------------
// RoPE in-place on q and k parts of g_qkv.
// ---------------------------------------------------------------------------
__global__ __launch_bounds__(256) void rope_kernel(
    const float* __restrict__ cosNK, const float* __restrict__ sinNK)
{
    const int t = blockIdx.x * blockDim.x + threadIdx.x;
    if (t >= NTOK * NH * 40) return;
    const int j = t % 40;
    const int h = (t / 40) % NH;
    const int n = t / (40 * NH);

    const float c1 = cosNK[n * HK + j];
    const float s1 = sinNK[n * HK + j];
    const float c2 = cosNK[n * HK + j + 40];
    const float s2 = sinNK[n * HK + j + 40];

    size_t base = (size_t)n * (3 * DM) + h * HK;
    {
        float x1 = g_qkv[base + j], x2 = g_qkv[base + j + 40];
        g_qkv[base + j]      = x1 * c1 - x2 * s1;
        g_qkv[base + j + 40] = x2 * c2 + x1 * s2;
    }
    base += DM;
    {
        float x1 = g_qkv[base + j], x2 = g_qkv[base + j + 40];
        g_qkv[base + j]      = x1 * c1 - x2 * s1;
        g_qkv[base + j + 40] = x2 * c2 + x1 * s2;
    }
}

// ---------------------------------------------------------------------------
// Tensor-core flash attention (bf16 3-split, online softmax in registers).
// Block: 128 threads (4 warps), 64 queries; loops 2048 keys in blocks of 64.
// Warp w owns query rows 16w..16w+15. K/V split to bf16 hi/lo in smem.
// ---------------------------------------------------------------------------
#define AP 88   // smem pitch (176B rows -> conflict-free ldmatrix)
#define ATT_SMEM (6 * 64 * AP * 2)

__global__ __launch_bounds__(128) void attn_mma(
    const float* __restrict__ qkv, float* __restrict__ ao)
{
    extern __shared__ __nv_bfloat16 smb2[];
    __nv_bfloat16* Qh = smb2;
    __nv_bfloat16* Ql = Qh + 64 * AP;
    __nv_bfloat16* Kh = Ql + 64 * AP;
    __nv_bfloat16* Kl = Kh + 64 * AP;
    __nv_bfloat16* Vh = Kl + 64 * AP;
    __nv_bfloat16* Vl = Vh + 64 * AP;

    const int tid = threadIdx.x;
    const int lane = tid & 31;
    const int warp = tid >> 5;
    const int qt = blockIdx.x, head = blockIdx.y, seg = blockIdx.z;
    const int n0 = seg * SEGL + qt * 64;

    // fold softmax scale and log2(e) into Q
    const float qscale = 0.1118033988749895f * 1.4426950408889634f;

    // load + prescale + split Q (64 x 80)
    for (int i = tid; i < 64 * 20; i += 128) {
        const int r = i / 20, c = i % 20;
        float4 v = *(const float4*)(qkv + (size_t)(n0 + r) * (3 * DM) + head * HK + c * 4);
        v.x *= qscale; v.y *= qscale; v.z *= qscale; v.w *= qscale;
        const int o = r * AP + c * 4;
        __nv_bfloat16 h0 = __float2bfloat16(v.x), h1 = __float2bfloat16(v.y);
        __nv_bfloat16 h2 = __float2bfloat16(v.z), h3 = __float2bfloat16(v.w);
        __nv_bfloat162 hp0 = {h0, h1}, hp1 = {h2, h3};
        *(__nv_bfloat162*)(Qh + o)     = hp0;
        *(__nv_bfloat162*)(Qh + o + 2) = hp1;
        __nv_bfloat162 lp0 = {__float2bfloat16(v.x - __bfloat162float(h0)),
                              __float2bfloat16(v.y - __bfloat162float(h1))};
        __nv_bfloat162 lp1 = {__float2bfloat16(v.z - __bfloat162float(h2)),
                              __float2bfloat16(v.w - __bfloat162float(h3))};
        *(__nv_bfloat162*)(Ql + o)     = lp0;
        *(__nv_bfloat162*)(Ql + o + 2) = lp1;
    }
    __syncthreads();

    // Q fragments held in registers across all key blocks
    uint32_t qfh[5][4], qfl[5][4];
    {
        const uint32_t uQh = smem_u32(Qh), uQl = smem_u32(Ql);
        const uint32_t qoff = (uint32_t)((warp * 16 + (lane & 15)) * AP + ((lane >> 4) << 3)) * 2;
#pragma unroll
        for (int ks = 0; ks < 5; ++ks) {
            const uint32_t ad = qoff + (uint32_t)(ks * 16 * 2);
            ldsm4(qfh[ks], uQh + ad);
            ldsm4(qfl[ks], uQl + ad);
        }
    }

    const uint32_t uKh = smem_u32(Kh), uKl = smem_u32(Kl);
    const uint32_t uVh = smem_u32(Vh), uVl = smem_u32(Vl);
    const uint32_t koff = (uint32_t)((lane & 15) * AP + ((lane >> 4) << 3)) * 2;
    const uint32_t voff = (uint32_t)((((lane & 7) + (((lane >> 3) & 1) << 3)) * AP) + ((lane >> 4) << 3)) * 2;

    float of[10][4];
#pragma unroll
    for (int t = 0; t < 10; t++)
#pragma unroll
        for (int j = 0; j < 4; j++) of[t][j] = 0.f;
    float m_a = -1e30f, m_b = -1e30f, l_a = 0.f, l_b = 0.f;

    for (int kb = 0; kb < SEGL / 64; ++kb) {
        __syncthreads();   // previous iter's ldsm reads done before overwrite
        const int nk = seg * SEGL + kb * 64;
        for (int i = tid; i < 64 * 20; i += 128) {
            const int r = i / 20, c = i % 20;
            const size_t gb = (size_t)(nk + r) * (3 * DM) + head * HK + c * 4;
            const int o = r * AP + c * 4;
            float4 kv4 = *(const float4*)(qkv + gb + DM);
            float4 vv4 = *(const float4*)(qkv + gb + 2 * DM);
            {
                __nv_bfloat16 h0 = __float2bfloat16(kv4.x), h1 = __float2bfloat16(kv4.y);
                __nv_bfloat16 h2 = __float2bfloat16(kv4.z), h3 = __float2bfloat16(kv4.w);
                __nv_bfloat162 hp0 = {h0, h1}, hp1 = {h2, h3};
                *(__nv_bfloat162*)(Kh + o)     = hp0;
                *(__nv_bfloat162*)(Kh + o + 2) = hp1;
                __nv_bfloat162 lp0 = {__float2bfloat16(kv4.x - __bfloat162float(h0)),
                                      __float2bfloat16(kv4.y - __bfloat162float(h1))};
                __nv_bfloat162 lp1 = {__float2bfloat16(kv4.z - __bfloat162float(h2)),
                                      __float2bfloat16(kv4.w - __bfloat162float(h3))};
                *(__nv_bfloat162*)(Kl + o)     = lp0;
                *(__nv_bfloat162*)(Kl + o + 2) = lp1;
            }
            {
                __nv_bfloat16 h0 = __float2bfloat16(vv4.x), h1 = __float2bfloat16(vv4.y);
                __nv_bfloat16 h2 = __float2bfloat16(vv4.z), h3 = __float2bfloat16(vv4.w);
                __nv_bfloat162 hp0 = {h0, h1}, hp1 = {h2, h3};
                *(__nv_bfloat162*)(Vh + o)     = hp0;
                *(__nv_bfloat162*)(Vh + o + 2) = hp1;
                __nv_bfloat162 lp0 = {__float2bfloat16(vv4.x - __bfloat162float(h0)),
                                      __float2bfloat16(vv4.y - __bfloat162float(h1))};
                __nv_bfloat162 lp1 = {__float2bfloat16(vv4.z - __bfloat162float(h2)),
                                      __float2bfloat16(vv4.w - __bfloat162float(h3))};
                *(__nv_bfloat162*)(Vl + o)     = lp0;
                *(__nv_bfloat162*)(Vl + o + 2) = lp1;
            }
        }
        __syncthreads();

        // ---- S = Q @ K^T (3-term) ----
        float s[8][4];
#pragma unroll
        for (int t = 0; t < 8; t++)
#pragma unroll
            for (int j = 0; j < 4; j++) s[t][j] = 0.f;

#pragma unroll
        for (int ks = 0; ks < 5; ++ks) {
#pragma unroll
            for (int g = 0; g < 4; ++g) {
                uint32_t kfh[4], kfl[4];
                const uint32_t ka = koff + (uint32_t)((g * 16 * AP + ks * 16) * 2);
                ldsm4(kfh, uKh + ka);
                ldsm4(kfl, uKl + ka);
#pragma unroll
                for (int h = 0; h < 2; ++h) {
                    float* d = s[2 * g + h];
                    mma16816(d, qfh[ks], kfh[h], kfh[h + 2]);
                    mma16816(d, qfh[ks], kfl[h], kfl[h + 2]);
                    mma16816(d, qfl[ks], kfh[h], kfh[h + 2]);
                }
            }
        }

        // ---- online softmax (exp2 domain) ----
        float rma = NEG_INF, rmb = NEG_INF;
#pragma unroll
        for (int t = 0; t < 8; t++) {
            rma = fmaxf(rma, fmaxf(s[t][0], s[t][1]));
            rmb = fmaxf(rmb, fmaxf(s[t][2], s[t][3]));
        }
        rma = fmaxf(rma, __shfl_xor_sync(0xffffffffu, rma, 1));
        rma = fmaxf(rma, __shfl_xor_sync(0xffffffffu, rma, 2));
        rmb = fmaxf(rmb, __shfl_xor_sync(0xffffffffu, rmb, 1));
        rmb = fmaxf(rmb, __shfl_xor_sync(0xffffffffu, rmb, 2));
        const float mna = fmaxf(m_a, rma), mnb = fmaxf(m_b, rmb);
        const float corra = exp2p(m_a - mna), corrb = exp2p(m_b - mnb);
        m_a = mna; m_b = mnb;

        float suma = 0.f, sumb = 0.f;
        uint32_t pha[8], phb[8], pla[8], plb[8];
#pragma unroll
        for (int t = 0; t < 8; t++) {
            const float p0 = exp2p(s[t][0] - m_a);
            const float p1 = exp2p(s[t][1] - m_a);
            const float p2 = exp2p(s[t][2] - m_b);
            const float p3 = exp2p(s[t][3] - m_b);
            suma += p0 + p1;
            sumb += p2 + p3;
            const uint32_t ha = cvt_bf2(p1, p0);
            const uint32_t hb = cvt_bf2(p3, p2);
            pha[t] = ha; phb[t] = hb;
            const float h0 = __int_as_float(ha << 16);
            const float h1 = __int_as_float(ha & 0xFFFF0000u);
            const float h2 = __int_as_float(hb << 16);
            const float h3 = __int_as_float(hb & 0xFFFF0000u);
            pla[t] = cvt_bf2(p1 - h1, p0 - h0);
            plb[t] = cvt_bf2(p3 - h3, p2 - h2);
        }
        suma += __shfl_xor_sync(0xffffffffu, suma, 1);
        suma += __shfl_xor_sync(0xffffffffu, suma, 2);
        sumb += __shfl_xor_sync(0xffffffffu, sumb, 1);
        sumb += __shfl_xor_sync(0xffffffffu, sumb, 2);
        l_a = l_a * corra + suma;
        l_b = l_b * corrb + sumb;
#pragma unroll
        for (int t = 0; t < 10; t++) {
            of[t][0] *= corra;
            of[t][1] *= corra;
            of[t][2] *= corrb;
            of[t][3] *= corrb;
        }

        // ---- O += P @ V (3-term) ----
#pragma unroll
        for (int ks = 0; ks < 4; ++ks) {
            const uint32_t ah2[4] = {pha[2 * ks], phb[2 * ks], pha[2 * ks + 1], phb[2 * ks + 1]};
            const uint32_t al2[4] = {pla[2 * ks], plb[2 * ks], pla[2 * ks + 1], plb[2 * ks + 1]};
#pragma unroll
            for (int g = 0; g < 5; ++g) {
                uint32_t vfh[4], vfl[4];
                const uint32_t va = voff + (uint32_t)((ks * 16 * AP + g * 16) * 2);
                ldsm4t(vfh, uVh + va);
                ldsm4t(vfl, uVl + va);
#pragma unroll
                for (int h = 0; h < 2; ++h) {
                    float* d = of[2 * g + h];
                    mma16816(d, ah2, vfh[2 * h], vfh[2 * h + 1]);
                    mma16816(d, ah2, vfl[2 * h], vfl[2 * h + 1]);
                    mma16816(d, al2, vfh[2 * h], vfh[2 * h + 1]);
                }
            }
        }
    }

    // ---- write normalized output ----
    const float inva = 1.f / l_a, invb = 1.f / l_b;
    const int rowa = n0 + warp * 16 + (lane >> 2);
    const int rowb = rowa + 8;
#pragma unroll
    for (int t = 0; t < 10; t++) {
        const int col = head * HK + t * 8 + 2 * (lane & 3);
        float2 va = {of[t][0] * inva, of[t][1] * inva};
        float2 vb = {of[t][2] * invb, of[t][3] * invb};
        *(float2*)(ao + (size_t)rowa * DM + col) = va;
        *(float2*)(ao + (size_t)rowb * DM + col) = vb;
    }
}

// ---------------------------------------------------------------------------
// Launch
// ---------------------------------------------------------------------------
extern "C" void kernel_launch(void* const* d_in, const int* in_sizes, int n_in,
                              void* d_out, int out_size)
{
    const float* hidden = (const float*)d_in[0];
    const float* cosNK  = (const float*)d_in[1];
    const float* sinNK  = (const float*)d_in[2];
    const float* qkv_w  = (const float*)d_in[3];
    const float* qkv_b  = (const float*)d_in[4];
    const float* proj_w = (const float*)d_in[5];
    const float* proj_b = (const float*)d_in[6];
    float* out = (float*)d_out;

    float *qkv = nullptr, *ao = nullptr;
    __nv_bfloat16 *ah = nullptr, *al = nullptr, *bh = nullptr, *bl = nullptr;
    cudaGetSymbolAddress((void**)&qkv, g_qkv);
    cudaGetSymbolAddress((void**)&ao,  g_ao);
    cudaGetSymbolAddress((void**)&ah,  g_ah);
    cudaGetSymbolAddress((void**)&al,  g_al);
    cudaGetSymbolAddress((void**)&bh,  g_bh);
    cudaGetSymbolAddress((void**)&bl,  g_bl);

    cudaFuncSetAttribute(gemm_mma, cudaFuncAttributeMaxDynamicSharedMemorySize, GSMEM);
    cudaFuncSetAttribute(attn_mma, cudaFuncAttributeMaxDynamicSharedMemorySize, ATT_SMEM);

    const int n4 = NTOK * DM / 4;

    // 1) prep GEMM1
    split_kernel<<<(n4 + 255) / 256, 256>>>(hidden, ah, al, n4);
    transpose_split_kernel<<<dim3(3 * DM / 32, DM / 32), dim3(32, 8)>>>(qkv_w, bh, bl, DM, 3 * DM);

    // 2) qkv = hidden @ qkv_w + qkv_b
    gemm_mma<<<dim3(3 * DM / 128, NTOK / 128), 256, GSMEM>>>(
        ah, al, bh, bl, qkv_b, qkv, 3 * DM, DM);

    // 3) RoPE
    {
        const int total = NTOK * NH * 40;
        rope_kernel<<<(total + 255) / 256, 256>>>(cosNK, sinNK);
    }

    // 4) attention (tensor cores)
    attn_mma<<<dim3(SEGL / 64, NH, NSEGS), 128, ATT_SMEM>>>(qkv, ao);

    // 5) prep GEMM2
    split_kernel<<<(n4 + 255) / 256, 256>>>(ao, ah, al, n4);
    transpose_split_kernel<<<dim3(DM / 32, DM / 32), dim3(32, 8)>>>(proj_w, bh, bl, DM, DM);

    // 6) out = ao @ proj_w + proj_b
    gemm_mma<<<dim3(DM / 128, NTOK / 128), 256, GSMEM>>>(
        ah, al, bh, bl, proj_b, out, DM, DM);
}

// round 7
// speedup vs baseline: 2.6739x; 1.1130x over previous
#include <cuda_runtime.h>
#include <cuda_bf16.h>
#include <cstdint>

// Problem constants (fixed by reference setup_inputs)
#define NTOK 16384
#define DM   1280
#define NH   16
#define HK   80
#define NSEGS 8
#define SEGL 2048

#define NEG_INF (__int_as_float(0xff800000))

// Scratch (allocation-free rule: __device__ globals)
__device__ float g_qkv[(size_t)NTOK * 3 * DM];            // [N][3*1280] fp32 (GEMM1 out)
__device__ __nv_bfloat16 g_ah[(size_t)NTOK * DM];         // GEMM A hi (hidden, then attn-out)
__device__ __nv_bfloat16 g_al[(size_t)NTOK * DM];         // GEMM A lo
__device__ __nv_bfloat16 g_bh[(size_t)3 * DM * DM];       // W^T hi [N][K]
__device__ __nv_bfloat16 g_bl[(size_t)3 * DM * DM];       // W^T lo [N][K]
__device__ __nv_bfloat16 g_qh[(size_t)NTOK * DM];         // q hi (rope'd, prescaled)
__device__ __nv_bfloat16 g_ql[(size_t)NTOK * DM];
__device__ __nv_bfloat16 g_kh[(size_t)NTOK * DM];         // k hi (rope'd)
__device__ __nv_bfloat16 g_kl[(size_t)NTOK * DM];
__device__ __nv_bfloat16 g_vh[(size_t)NTOK * DM];         // v hi
__device__ __nv_bfloat16 g_vl[(size_t)NTOK * DM];

// ---------------------------------------------------------------------------
// helpers
// ---------------------------------------------------------------------------
__device__ __forceinline__ uint32_t smem_u32(const void* p) {
    uint32_t a;
    asm("{ .reg .u64 t; cvta.to.shared.u64 t, %1; cvt.u32.u64 %0, t; }" : "=r"(a) : "l"(p));
    return a;
}
__device__ __forceinline__ void ldsm4(uint32_t* r, uint32_t addr) {
    asm volatile("ldmatrix.sync.aligned.m8n8.x4.shared.b16 {%0,%1,%2,%3}, [%4];"
                 : "=r"(r[0]), "=r"(r[1]), "=r"(r[2]), "=r"(r[3]) : "r"(addr));
}
__device__ __forceinline__ void ldsm4t(uint32_t* r, uint32_t addr) {
    asm volatile("ldmatrix.sync.aligned.m8n8.x4.trans.shared.b16 {%0,%1,%2,%3}, [%4];"
                 : "=r"(r[0]), "=r"(r[1]), "=r"(r[2]), "=r"(r[3]) : "r"(addr));
}
__device__ __forceinline__ void mma16816(float* d, const uint32_t* a, uint32_t b0, uint32_t b1) {
    asm volatile("mma.sync.aligned.m16n8k16.row.col.f32.bf16.bf16.f32 "
                 "{%0,%1,%2,%3}, {%4,%5,%6,%7}, {%8,%9}, {%0,%1,%2,%3};"
                 : "+f"(d[0]), "+f"(d[1]), "+f"(d[2]), "+f"(d[3])
                 : "r"(a[0]), "r"(a[1]), "r"(a[2]), "r"(a[3]), "r"(b0), "r"(b1));
}
__device__ __forceinline__ uint32_t cvt_bf2(float hi, float lo) {
    uint32_t d;
    asm("cvt.rn.bf16x2.f32 %0, %1, %2;" : "=r"(d) : "f"(hi), "f"(lo));
    return d;
}
__device__ __forceinline__ void cpa16(uint32_t dst, const void* src) {
    asm volatile("cp.async.cg.shared.global [%0], [%1], 16;" :: "r"(dst), "l"(src));
}
#define CP_COMMIT() asm volatile("cp.async.commit_group;")
#define CP_WAIT0()  asm volatile("cp.async.wait_group 0;")
// FMA-pipe exp2 for t <= 0 (clamped), ~3e-6 rel error
__device__ __forceinline__ float exp2p(float t) {
    t = fmaxf(t, -126.f);
    const float z = t + 12582912.f;
    const int n = __float_as_int(z) - 0x4B400000;
    const float f = t - (z - 12582912.f);
    float r = 1.3333558146e-3f;
    r = fmaf(r, f, 9.6181291076e-3f);
    r = fmaf(r, f, 5.5504108664e-2f);
    r = fmaf(r, f, 2.4022650695e-1f);
    r = fmaf(r, f, 6.9314718055e-1f);
    r = fmaf(r, f, 1.0f);
    return __int_as_float(__float_as_int(r) + (n << 23));
}
__device__ __forceinline__ void split_store(__nv_bfloat16* hp, __nv_bfloat16* lp,
                                            size_t o, float v) {
    const __nv_bfloat16 h = __float2bfloat16(v);
    hp[o] = h;
    lp[o] = __float2bfloat16(v - __bfloat162float(h));
}

// ---------------------------------------------------------------------------
// split: fp32 -> bf16 hi + bf16 lo, vectorized by 4
// ---------------------------------------------------------------------------
__global__ __launch_bounds__(256) void split_kernel(
    const float* __restrict__ in, __nv_bfloat16* __restrict__ hi,
    __nv_bfloat16* __restrict__ lo, int n4)
{
    const int i = blockIdx.x * blockDim.x + threadIdx.x;
    if (i >= n4) return;
    const float4 v = ((const float4*)in)[i];
    __nv_bfloat16 h0 = __float2bfloat16(v.x);
    __nv_bfloat16 h1 = __float2bfloat16(v.y);
    __nv_bfloat16 h2 = __float2bfloat16(v.z);
    __nv_bfloat16 h3 = __float2bfloat16(v.w);
    __nv_bfloat162 hp0 = {h0, h1}, hp1 = {h2, h3};
    __nv_bfloat162 lp0 = {__float2bfloat16(v.x - __bfloat162float(h0)),
                          __float2bfloat16(v.y - __bfloat162float(h1))};
    __nv_bfloat162 lp1 = {__float2bfloat16(v.z - __bfloat162float(h2)),
                          __float2bfloat16(v.w - __bfloat162float(h3))};
    ((__nv_bfloat162*)hi)[i * 2 + 0] = hp0;
    ((__nv_bfloat162*)hi)[i * 2 + 1] = hp1;
    ((__nv_bfloat162*)lo)[i * 2 + 0] = lp0;
    ((__nv_bfloat162*)lo)[i * 2 + 1] = lp1;
}

// ---------------------------------------------------------------------------
// transpose + split: W[K][N] row-major -> WT hi/lo [N][K] bf16
// ---------------------------------------------------------------------------
__global__ void transpose_split_kernel(
    const float* __restrict__ W, __nv_bfloat16* __restrict__ bh,
    __nv_bfloat16* __restrict__ bl, int Krows, int Ncols)
{
    __shared__ float t[32][33];
    const int bx = blockIdx.x * 32;
    const int by = blockIdx.y * 32;
    const int x = threadIdx.x, y = threadIdx.y;
#pragma unroll
    for (int i = 0; i < 32; i += 8)
        t[y + i][x] = W[(size_t)(by + y + i) * Ncols + bx + x];
    __syncthreads();
#pragma unroll
    for (int i = 0; i < 32; i += 8) {
        const float v = t[x][y + i];
        split_store(bh, bl, (size_t)(bx + y + i) * Krows + by + x, v);
    }
}

// ---------------------------------------------------------------------------
// fused RoPE + bf16 split: g_qkv -> qh/ql (prescaled), kh/kl, vh/vl
// ---------------------------------------------------------------------------
__global__ __launch_bounds__(256) void rope_split_kernel(
    const float* __restrict__ qkv, const float* __restrict__ cosNK,
    const float* __restrict__ sinNK,
    __nv_bfloat16* __restrict__ qh, __nv_bfloat16* __restrict__ ql,
    __nv_bfloat16* __restrict__ kh, __nv_bfloat16* __restrict__ kl,
    __nv_bfloat16* __restrict__ vh, __nv_bfloat16* __restrict__ vl)
{
    const int t = blockIdx.x * blockDim.x + threadIdx.x;
    if (t >= NTOK * NH * 40) return;
    const int j = t % 40;
    const int h = (t / 40) % NH;
    const int n = t / (40 * NH);

    const float c1 = cosNK[n * HK + j];
    const float s1 = sinNK[n * HK + j];
    const float c2 = cosNK[n * HK + j + 40];
    const float s2 = sinNK[n * HK + j + 40];

    const size_t ib = (size_t)n * (3 * DM) + h * HK;
    const size_t ob = (size_t)n * DM + h * HK;
    const float qs = 0.1118033988749895f * 1.4426950408889634f;  // scale * log2(e)

    // q (rope + prescale)
    {
        const float x1 = qkv[ib + j], x2 = qkv[ib + j + 40];
        split_store(qh, ql, ob + j,      (x1 * c1 - x2 * s1) * qs);
        split_store(qh, ql, ob + j + 40, (x2 * c2 + x1 * s2) * qs);
    }
    // k (rope)
    {
        const float x1 = qkv[ib + DM + j], x2 = qkv[ib + DM + j + 40];
        split_store(kh, kl, ob + j,      x1 * c1 - x2 * s1);
        split_store(kh, kl, ob + j + 40, x2 * c2 + x1 * s2);
    }
    // v (copy)
    {
        split_store(vh, vl, ob + j,      qkv[ib + 2 * DM + j]);
        split_store(vh, vl, ob + j + 40, qkv[ib + 2 * DM + j + 40]);
    }
}

// ---------------------------------------------------------------------------
// bf16 3-split tensor-core GEMM + bias, cp.async double-buffered
// ---------------------------------------------------------------------------
#define GP 40
#define BUFE (128 * GP)
#define GSMEM (8 * BUFE * 2)

__global__ __launch_bounds__(256) void gemm_mma(
    const __nv_bfloat16* __restrict__ Ah, const __nv_bfloat16* __restrict__ Al,
    const __nv_bfloat16* __restrict__ Bh, const __nv_bfloat16* __restrict__ Bl,
    const float* __restrict__ bias, float* __restrict__ C, int N, int Kd)
{
    extern __shared__ __nv_bfloat16 smb[];
    __nv_bfloat16* Ash = smb;
    __nv_bfloat16* Asl = Ash + 2 * BUFE;
    __nv_bfloat16* Bsh = Asl + 2 * BUFE;
    __nv_bfloat16* Bsl = Bsh + 2 * BUFE;

    const int tid = threadIdx.x;
    const int lane = tid & 31;
    const int warp = tid >> 5;
    const int wm = warp >> 1;
    const int wn = warp & 1;
    const int m0 = blockIdx.y * 128;
    const int n0 = blockIdx.x * 128;

    const int r0 = tid >> 2;
    const int sg = (tid & 3) * 8;

    const __nv_bfloat16* pAh = Ah + (size_t)(m0 + r0) * Kd + sg;
    const __nv_bfloat16* pAl = Al + (size_t)(m0 + r0) * Kd + sg;
    const __nv_bfloat16* pBh = Bh + (size_t)(n0 + r0) * Kd + sg;
    const __nv_bfloat16* pBl = Bl + (size_t)(n0 + r0) * Kd + sg;
    const size_t rstep = (size_t)64 * Kd;

    const uint32_t uAsh = smem_u32(Ash);
    const uint32_t uAsl = smem_u32(Asl);
    const uint32_t uBsh = smem_u32(Bsh);
    const uint32_t uBsl = smem_u32(Bsl);

    float acc[2][8][4];
#pragma unroll
    for (int a = 0; a < 2; a++)
#pragma unroll
        for (int b = 0; b < 8; b++)
#pragma unroll
            for (int c = 0; c < 4; c++) acc[a][b][c] = 0.f;

    auto issue = [&](int k0, int buf) {
        const uint32_t o0 = (uint32_t)(buf * BUFE + r0 * GP + sg) * 2;
        const uint32_t o1 = (uint32_t)(buf * BUFE + (r0 + 64) * GP + sg) * 2;
        cpa16(uAsh + o0, pAh + k0);  cpa16(uAsh + o1, pAh + k0 + rstep);
        cpa16(uAsl + o0, pAl + k0);  cpa16(uAsl + o1, pAl + k0 + rstep);
        cpa16(uBsh + o0, pBh + k0);  cpa16(uBsh + o1, pBh + k0 + rstep);
        cpa16(uBsl + o0, pBl + k0);  cpa16(uBsl + o1, pBl + k0 + rstep);
        CP_COMMIT();
    };

    const uint32_t aoff = (uint32_t)((wm * 32 + (lane & 15)) * GP + ((lane >> 4) << 3)) * 2;
    const uint32_t boff = (uint32_t)((wn * 64 + (lane & 15)) * GP + ((lane >> 4) << 3)) * 2;

    const int NT = Kd >> 5;
    issue(0, 0);

    for (int t = 0; t < NT; ++t) {
        CP_WAIT0();
        __syncthreads();
        if (t + 1 < NT) issue((t + 1) << 5, (t + 1) & 1);

        const uint32_t bb = (uint32_t)((t & 1) * BUFE * 2);
#pragma unroll
        for (int ks = 0; ks < 2; ++ks) {
            const uint32_t kso = (uint32_t)(ks * 16 * 2);
            uint32_t ah[2][4], al[2][4];
#pragma unroll
            for (int t2 = 0; t2 < 2; ++t2) {
                const uint32_t ad = bb + aoff + kso + (uint32_t)(t2 * 16 * GP * 2);
                ldsm4(ah[t2], uAsh + ad);
                ldsm4(al[t2], uAsl + ad);
            }
            uint32_t bh4[4][4], bl4[4][4];
#pragma unroll
            for (int g = 0; g < 4; ++g) {
                const uint32_t bd = bb + boff + kso + (uint32_t)(g * 16 * GP * 2);
                ldsm4(bh4[g], uBsh + bd);
                ldsm4(bl4[g], uBsl + bd);
            }
#pragma unroll
            for (int t2 = 0; t2 < 2; ++t2)
#pragma unroll
                for (int g = 0; g < 4; ++g)
#pragma unroll
                    for (int h = 0; h < 2; ++h) {
                        float* d = acc[t2][g * 2 + h];
                        mma16816(d, ah[t2], bh4[g][h], bh4[g][h + 2]);
                        mma16816(d, ah[t2], bl4[g][h], bl4[g][h + 2]);
                        mma16816(d, al[t2], bh4[g][h], bh4[g][h + 2]);
                    }
        }
    }

#pragma unroll
    for (int t2 = 0; t2 < 2; ++t2) {
        const int row = m0 + wm * 32 + t2 * 16 + (lane >> 2);
#pragma unroll
        for (int n8 = 0; n8 < 8; ++n8) {
            const int col = n0 + wn * 64 + n8 * 8 + (lane & 3) * 2;
            const float b0 = __ldg(bias + col);
            const float b1 = __ldg(bias + col + 1);
            float2 v0 = {acc[t2][n8][0] + b0, acc[t2][n8][1] + b1};
            float2 v1 = {acc[t2][n8][2] + b0, acc[t2][n8][3] + b1};
            *(float2*)(C + (size_t)row * N + col) = v0;
            *(float2*)(C + (size_t)(row + 8) * N + col) = v1;
        }
    }
}

// ---------------------------------------------------------------------------
// Tensor-core flash attention, pre-split bf16 inputs, cp.async double-buffered.
// Block: 128 threads (4 warps), 64 queries; 2048 keys in blocks of 64.
// Epilogue writes bf16 hi/lo (GEMM2 A operand) directly.
// ---------------------------------------------------------------------------
#define AP 88
#define KVB (64 * AP)
#define ATT_SMEM ((2 + 8) * KVB * 2)

__global__ __launch_bounds__(128) void attn_mma(
    const __nv_bfloat16* __restrict__ qh, const __nv_bfloat16* __restrict__ ql,
    const __nv_bfloat16* __restrict__ kh, const __nv_bfloat16* __restrict__ kl,
    const __nv_bfloat16* __restrict__ vh, const __nv_bfloat16* __restrict__ vl,
    __nv_bfloat16* __restrict__ oh, __nv_bfloat16* __restrict__ ol)
{
    extern __shared__ __nv_bfloat16 smb2[];
    __nv_bfloat16* Qh = smb2;            // [64][AP]
    __nv_bfloat16* Ql = Qh + KVB;
    __nv_bfloat16* KV = Ql + KVB;        // [2 buf][4 arr][64][AP]  arr: Kh,Kl,Vh,Vl

    const int tid = threadIdx.x;
    const int lane = tid & 31;
    const int warp = tid >> 5;
    const int qt = blockIdx.x, head = blockIdx.y, seg = blockIdx.z;
    const int n0 = seg * SEGL + qt * 64;

    const uint32_t uKV = smem_u32(KV);

    auto issueKV = [&](int kb, int buf) {
        const int nk = seg * SEGL + kb * 64;
        const uint32_t bofs = (uint32_t)(buf * 4 * KVB) * 2;
#pragma unroll
        for (int i = 0; i < 5; ++i) {
            const int idx = tid + i * 128;
            const int r = idx / 10, c = idx % 10;
            const uint32_t d = bofs + (uint32_t)(r * AP + c * 8) * 2 + uKV;
            const size_t g = (size_t)(nk + r) * DM + head * HK + c * 8;
            cpa16(d + 0 * KVB * 2, kh + g);
            cpa16(d + 1 * KVB * 2, kl + g);
            cpa16(d + 2 * KVB * 2, vh + g);
            cpa16(d + 3 * KVB * 2, vl + g);
        }
        CP_COMMIT();
    };

    issueKV(0, 0);

    // load Q tile (pre-scaled, pre-split)
#pragma unroll
    for (int i = 0; i < 5; ++i) {
        const int idx = tid + i * 128;
        const int r = idx / 10, c = idx % 10;
        const size_t g = (size_t)(n0 + r) * DM + head * HK + c * 8;
        *(uint4*)(Qh + r * AP + c * 8) = *(const uint4*)(qh + g);
        *(uint4*)(Ql + r * AP + c * 8) = *(const uint4*)(ql + g);
    }
    __syncthreads();

    uint32_t qfh[5][4], qfl[5][4];
    {
        const uint32_t uQh = smem_u32(Qh), uQl = smem_u32(Ql);
        const uint32_t qoff = (uint32_t)((warp * 16 + (lane & 15)) * AP + ((lane >> 4) << 3)) * 2;
#pragma unroll
        for (int ks = 0; ks < 5; ++ks) {
            const uint32_t ad = qoff + (uint32_t)(ks * 16 * 2);
            ldsm4(qfh[ks], uQh + ad);
            ldsm4(qfl[ks], uQl + ad);
        }
    }

    const uint32_t koff = (uint32_t)((lane & 15) * AP + ((lane >> 4) << 3)) * 2;
    const uint32_t voff = (uint32_t)((((lane & 7) + (((lane >> 3) & 1) << 3)) * AP) + ((lane >> 4) << 3)) * 2;

    float of[10][4];
#pragma unroll
    for (int t = 0; t < 10; t++)
#pragma unroll
        for (int j = 0; j < 4; j++) of[t][j] = 0.f;
    float m_a = -1e30f, m_b = -1e30f, l_a = 0.f, l_b = 0.f;

    for (int kb = 0; kb < SEGL / 64; ++kb) {
        CP_WAIT0();
        __syncthreads();
        if (kb + 1 < SEGL / 64) issueKV(kb + 1, (kb + 1) & 1);

        const uint32_t bb = (uint32_t)((kb & 1) * 4 * KVB) * 2;
        const uint32_t uKh = uKV + bb;
        const uint32_t uKl = uKh + KVB * 2;
        const uint32_t uVh = uKl + KVB * 2;
        const uint32_t uVl = uVh + KVB * 2;

        // ---- S = Q @ K^T (3-term) ----
        float s[8][4];
#pragma unroll
        for (int t = 0; t < 8; t++)
#pragma unroll
            for (int j = 0; j < 4; j++) s[t][j] = 0.f;

#pragma unroll
        for (int ks = 0; ks < 5; ++ks) {
#pragma unroll
            for (int g = 0; g < 4; ++g) {
                uint32_t kfh[4], kfl[4];
                const uint32_t ka = koff + (uint32_t)((g * 16 * AP + ks * 16) * 2);
                ldsm4(kfh, uKh + ka);
                ldsm4(kfl, uKl + ka);
#pragma unroll
                for (int h = 0; h < 2; ++h) {
                    float* d = s[2 * g + h];
                    mma16816(d, qfh[ks], kfh[h], kfh[h + 2]);
                    mma16816(d, qfh[ks], kfl[h], kfl[h + 2]);
                    mma16816(d, qfl[ks], kfh[h], kfh[h + 2]);
                }
            }
        }

        // ---- online softmax (exp2 domain) ----
        float rma = NEG_INF, rmb = NEG_INF;
#pragma unroll
        for (int t = 0; t < 8; t++) {
            rma = fmaxf(rma, fmaxf(s[t][0], s[t][1]));
            rmb = fmaxf(rmb, fmaxf(s[t][2], s[t][3]));
        }
        rma = fmaxf(rma, __shfl_xor_sync(0xffffffffu, rma, 1));
        rma = fmaxf(rma, __shfl_xor_sync(0xffffffffu, rma, 2));
        rmb = fmaxf(rmb, __shfl_xor_sync(0xffffffffu, rmb, 1));
        rmb = fmaxf(rmb, __shfl_xor_sync(0xffffffffu, rmb, 2));
        const float mna = fmaxf(m_a, rma), mnb = fmaxf(m_b, rmb);
        const float corra = exp2p(m_a - mna), corrb = exp2p(m_b - mnb);
        m_a = mna; m_b = mnb;

        float suma = 0.f, sumb = 0.f;
        uint32_t pha[8], phb[8], pla[8], plb[8];
#pragma unroll
        for (int t = 0; t < 8; t++) {
            const float p0 = exp2p(s[t][0] - m_a);
            const float p1 = exp2p(s[t][1] - m_a);
            const float p2 = exp2p(s[t][2] - m_b);
            const float p3 = exp2p(s[t][3] - m_b);
            suma += p0 + p1;
            sumb += p2 + p3;
            const uint32_t ha = cvt_bf2(p1, p0);
            const uint32_t hb = cvt_bf2(p3, p2);
            pha[t] = ha; phb[t] = hb;
            const float h0 = __int_as_float(ha << 16);
            const float h1 = __int_as_float(ha & 0xFFFF0000u);
            const float h2 = __int_as_float(hb << 16);
            const float h3 = __int_as_float(hb & 0xFFFF0000u);
            pla[t] = cvt_bf2(p1 - h1, p0 - h0);
            plb[t] = cvt_bf2(p3 - h3, p2 - h2);
        }
        suma += __shfl_xor_sync(0xffffffffu, suma, 1);
        suma += __shfl_xor_sync(0xffffffffu, suma, 2);
        sumb += __shfl_xor_sync(0xffffffffu, sumb, 1);
        sumb += __shfl_xor_sync(0xffffffffu, sumb, 2);
        l_a = l_a * corra + suma;
        l_b = l_b * corrb + sumb;
#pragma unroll
        for (int t = 0; t < 10; t++) {
            of[t][0] *= corra;
            of[t][1] *= corra;
            of[t][2] *= corrb;
            of[t][3] *= corrb;
        }

        // ---- O += P @ V (3-term) ----
#pragma unroll
        for (int ks = 0; ks < 4; ++ks) {
            const uint32_t ah2[4] = {pha[2 * ks], phb[2 * ks], pha[2 * ks + 1], phb[2 * ks + 1]};
            const uint32_t al2[4] = {pla[2 * ks], plb[2 * ks], pla[2 * ks + 1], plb[2 * ks + 1]};
#pragma unroll
            for (int g = 0; g < 5; ++g) {
                uint32_t vfh[4], vfl[4];
                const uint32_t va = voff + (uint32_t)((ks * 16 * AP + g * 16) * 2);
                ldsm4t(vfh, uVh + va);
                ldsm4t(vfl, uVl + va);
#pragma unroll
                for (int h = 0; h < 2; ++h) {
                    float* d = of[2 * g + h];
                    mma16816(d, ah2, vfh[2 * h], vfh[2 * h + 1]);
                    mma16816(d, ah2, vfl[2 * h], vfl[2 * h + 1]);
                    mma16816(d, al2, vfh[2 * h], vfh[2 * h + 1]);
                }
            }
        }
    }

    // ---- write normalized output as bf16 hi/lo (GEMM2 A operand) ----
    const float inva = 1.f / l_a, invb = 1.f / l_b;
    const int rowa = n0 + warp * 16 + (lane >> 2);
    const int rowb = rowa + 8;
#pragma unroll
    for (int t = 0; t < 10; t++) {
        const int col = head * HK + t * 8 + 2 * (lane & 3);
        const float a0 = of[t][0] * inva, a1 = of[t][1] * inva;
        const float b0 = of[t][2] * invb, b1 = of[t][3] * invb;
        const __nv_bfloat16 ah0 = __float2bfloat16(a0), ah1 = __float2bfloat16(a1);
        const __nv_bfloat16 bh0 = __float2bfloat16(b0), bh1 = __float2bfloat16(b1);
        __nv_bfloat162 vha = {ah0, ah1};
        __nv_bfloat162 vla = {__float2bfloat16(a0 - __bfloat162float(ah0)),
                              __float2bfloat16(a1 - __bfloat162float(ah1))};
        __nv_bfloat162 vhb = {bh0, bh1};
        __nv_bfloat162 vlb = {__float2bfloat16(b0 - __bfloat162float(bh0)),
                              __float2bfloat16(b1 - __bfloat162float(bh1))};
        *(__nv_bfloat162*)(oh + (size_t)rowa * DM + col) = vha;
        *(__nv_bfloat162*)(ol + (size_t)rowa * DM + col) = vla;
        *(__nv_bfloat162*)(oh + (size_t)rowb * DM + col) = vhb;
        *(__nv_bfloat162*)(ol + (size_t)rowb * DM + col) = vlb;
    }
}

// ---------------------------------------------------------------------------
// Launch
// ---------------------------------------------------------------------------
extern "C" void kernel_launch(void* const* d_in, const int* in_sizes, int n_in,
                              void* d_out, int out_size)
{
    const float* hidden = (const float*)d_in[0];
    const float* cosNK  = (const float*)d_in[1];
    const float* sinNK  = (const float*)d_in[2];
    const float* qkv_w  = (const float*)d_in[3];
    const float* qkv_b  = (const float*)d_in[4];
    const float* proj_w = (const float*)d_in[5];
    const float* proj_b = (const float*)d_in[6];
    float* out = (float*)d_out;

    float* qkv = nullptr;
    __nv_bfloat16 *ah, *al, *bh, *bl, *qh, *ql, *kh, *kl, *vh, *vl;
    cudaGetSymbolAddress((void**)&qkv, g_qkv);
    cudaGetSymbolAddress((void**)&ah,  g_ah);
    cudaGetSymbolAddress((void**)&al,  g_al);
    cudaGetSymbolAddress((void**)&bh,  g_bh);
    cudaGetSymbolAddress((void**)&bl,  g_bl);
    cudaGetSymbolAddress((void**)&qh,  g_qh);
    cudaGetSymbolAddress((void**)&ql,  g_ql);
    cudaGetSymbolAddress((void**)&kh,  g_kh);
    cudaGetSymbolAddress((void**)&kl,  g_kl);
    cudaGetSymbolAddress((void**)&vh,  g_vh);
    cudaGetSymbolAddress((void**)&vl,  g_vl);

    cudaFuncSetAttribute(gemm_mma, cudaFuncAttributeMaxDynamicSharedMemorySize, GSMEM);
    cudaFuncSetAttribute(attn_mma, cudaFuncAttributeMaxDynamicSharedMemorySize, ATT_SMEM);

    const int n4 = NTOK * DM / 4;

    // 1) prep GEMM1: split hidden, transpose+split qkv_w
    split_kernel<<<(n4 + 255) / 256, 256>>>(hidden, ah, al, n4);
    transpose_split_kernel<<<dim3(3 * DM / 32, DM / 32), dim3(32, 8)>>>(qkv_w, bh, bl, DM, 3 * DM);

    // 2) qkv = hidden @ qkv_w + qkv_b
    gemm_mma<<<dim3(3 * DM / 128, NTOK / 128), 256, GSMEM>>>(
        ah, al, bh, bl, qkv_b, qkv, 3 * DM, DM);

    // 3) fused RoPE + split to bf16 hi/lo
    {
        const int total = NTOK * NH * 40;
        rope_split_kernel<<<(total + 255) / 256, 256>>>(qkv, cosNK, sinNK,
                                                        qh, ql, kh, kl, vh, vl);
    }

    // 4) attention (tensor cores, async pipeline); writes GEMM2's A hi/lo
    attn_mma<<<dim3(SEGL / 64, NH, NSEGS), 128, ATT_SMEM>>>(
        qh, ql, kh, kl, vh, vl, ah, al);

    // 5) prep GEMM2 weights
    transpose_split_kernel<<<dim3(DM / 32, DM / 32), dim3(32, 8)>>>(proj_w, bh, bl, DM, DM);

    // 6) out = attn_out @ proj_w + proj_b
    gemm_mma<<<dim3(DM / 128, NTOK / 128), 256, GSMEM>>>(
        ah, al, bh, bl, proj_b, out, DM, DM);
}